// round 1
// baseline (speedup 1.0000x reference)
#include <cuda_runtime.h>

#define T 24
#define TPAD 26
#define D 64
#define KW 3
#define ROWS_PER_BLOCK 16
#define BLOCK_THREADS 256

// Folded weights: M[k][i][o2] = sum_o W_lin[o2,o] * W_conv[o,i,0,k]
__device__ float g_M[KW * D * D];
// c[o2] = sum_o W_lin[o2,o] * b_conv[o]
__device__ float g_c[D];

__global__ void prep_kernel(const float* __restrict__ W_conv,
                            const float* __restrict__ b_conv,
                            const float* __restrict__ W_lin) {
    int gid = blockIdx.x * blockDim.x + threadIdx.x;
    if (gid < KW * D * D) {
        int k   = gid / (D * D);
        int rem = gid % (D * D);
        int i   = rem / D;
        int o2  = rem % D;
        float s = 0.f;
#pragma unroll 8
        for (int o = 0; o < D; ++o) {
            // W_conv shape (D_out, D_in, 1, KW): flat o*(D*KW) + i*KW + k
            s += W_lin[o2 * D + o] * W_conv[o * (D * KW) + i * KW + k];
        }
        g_M[gid] = s;  // layout [k][i][o2] -> o2-contiguous
    }
    if (gid < D) {
        float s = 0.f;
#pragma unroll 8
        for (int o = 0; o < D; ++o) s += W_lin[gid * D + o] * b_conv[o];
        g_c[gid] = s;
    }
}

__global__ __launch_bounds__(BLOCK_THREADS, 4)
void temporal_agg_kernel(const float* __restrict__ val,
                         const float* __restrict__ b_lin,
                         float* __restrict__ out,
                         int rows_total) {
    __shared__ float sval[TPAD * D];  // padded value row: row 0 and row 25 are zero halo
    __shared__ float sg[T * D];       // g[tau][o2]

    const int tid = threadIdx.x;
    const int q   = tid >> 6;    // t-quarter: 0..3
    const int o2  = tid & 63;    // output channel

    // zero the halo rows once (never overwritten)
    if (tid < D) {
        sval[tid] = 0.f;
        sval[(TPAD - 1) * D + tid] = 0.f;
    }

    const float cc = g_c[o2];
    const float bl = __ldg(&b_lin[o2]);
    const int tbase = q * 6;

    __syncthreads();

    for (int r = 0; r < ROWS_PER_BLOCK; ++r) {
        const int row = blockIdx.x * ROWS_PER_BLOCK + r;
        if (row >= rows_total) break;

        // stage value row: 1536 floats = 384 float4, coalesced
        const float4* src = (const float4*)(val + (size_t)row * (T * D));
        float4* dst = (float4*)(sval + D);  // interior starts at padded row 1
        dst[tid] = src[tid];
        if (tid < (T * D / 4) - BLOCK_THREADS) dst[tid + BLOCK_THREADS] = src[tid + BLOCK_THREADS];
        __syncthreads();

        // g[tau, o2] = sum_{i,k} M[o2,i,k] * val[tau+k-1, i]
        float acc[6];
#pragma unroll
        for (int t6 = 0; t6 < 6; ++t6) acc[t6] = 0.f;

#pragma unroll 4
        for (int i = 0; i < D; ++i) {
            float v[8];  // padded rows tbase .. tbase+7 (covers tau+k for tau in [tbase,tbase+5], k in [0,2])
#pragma unroll
            for (int j = 0; j < 8; ++j) v[j] = sval[(tbase + j) * D + i];  // warp-broadcast LDS
#pragma unroll
            for (int k = 0; k < KW; ++k) {
                float m = __ldg(&g_M[(k * D + i) * D + o2]);  // L1-resident, conflict-free
#pragma unroll
                for (int t6 = 0; t6 < 6; ++t6)
                    acc[t6] = fmaf(m, v[t6 + k], acc[t6]);
            }
        }

        // stash g (sg disjoint from sval: no hazard before this sync)
#pragma unroll
        for (int t6 = 0; t6 < 6; ++t6) sg[(tbase + t6) * D + o2] = acc[t6];
        __syncthreads();

        // band-sum over t, boundary-aware bias, relu, store
        float* orow = out + (size_t)row * (T * D);
#pragma unroll
        for (int t6 = 0; t6 < 6; ++t6) {
            const int t = tbase + t6;
            float z = sg[t * D + o2];
            float nb = 3.f;
            if (t > 0)     z += sg[(t - 1) * D + o2]; else nb -= 1.f;
            if (t < T - 1) z += sg[(t + 1) * D + o2]; else nb -= 1.f;
            float o = fmaf(nb, cc, z) + bl;
            orow[t * D + o2] = fmaxf(o, 0.f);
        }
        __syncthreads();  // protect sval/sg for next row
    }
}

extern "C" void kernel_launch(void* const* d_in, const int* in_sizes, int n_in,
                              void* d_out, int out_size) {
    const float* value  = (const float*)d_in[0];
    const float* W_conv = (const float*)d_in[1];
    const float* b_conv = (const float*)d_in[2];
    const float* W_lin  = (const float*)d_in[3];
    const float* b_lin  = (const float*)d_in[4];
    float* out = (float*)d_out;

    const int rows_total = in_sizes[0] / (T * D);  // B*N = 16384

    prep_kernel<<<(KW * D * D + 255) / 256, 256>>>(W_conv, b_conv, W_lin);

    const int grid = (rows_total + ROWS_PER_BLOCK - 1) / ROWS_PER_BLOCK;  // 1024
    temporal_agg_kernel<<<grid, BLOCK_THREADS>>>(value, b_lin, out, rows_total);
}

// round 3
// speedup vs baseline: 1.3241x; 1.3241x over previous
#include <cuda_runtime.h>
#include <cstdint>

#define T 24
#define D 64
#define KW 3
#define WARPS 6
#define BLOCK (WARPS * 32)
#define STRIDE 68          // padded floats per t-row: breaks tg bank collision, mult of 4 for float4

// Folded weights: g_M[k][i][o2] = sum_o W_lin[o2,o] * W_conv[o,i,0,k]  (o2-contiguous -> natural f32 pairs)
__device__ float g_M[KW * D * D];
__device__ float g_c[D];   // c[o2] = sum_o W_lin[o2,o] * b_conv[o]

__global__ void prep_kernel(const float* __restrict__ W_conv,
                            const float* __restrict__ b_conv,
                            const float* __restrict__ W_lin) {
    int gid = blockIdx.x * blockDim.x + threadIdx.x;
    if (gid < KW * D * D) {
        int k   = gid / (D * D);
        int rem = gid % (D * D);
        int i   = rem / D;
        int o2  = rem % D;
        float s = 0.f;
#pragma unroll 8
        for (int o = 0; o < D; ++o)
            s += W_lin[o2 * D + o] * W_conv[o * (D * KW) + i * KW + k];
        g_M[gid] = s;
    }
    if (gid < D) {
        float s = 0.f;
#pragma unroll 8
        for (int o = 0; o < D; ++o) s += W_lin[gid * D + o] * b_conv[o];
        g_c[gid] = s;
    }
}

__device__ __forceinline__ uint64_t pack2(float x) {
    uint64_t d;
    asm("mov.b64 %0, {%1, %1};" : "=l"(d) : "f"(x));
    return d;
}
__device__ __forceinline__ void fma2(uint64_t& a, uint64_t m, uint64_t v) {
    asm("fma.rn.f32x2 %0, %1, %2, %0;" : "+l"(a) : "l"(m), "l"(v));
}
__device__ __forceinline__ float2 as_f2(uint64_t x) {
    float2 f;
    asm("mov.b64 {%0, %1}, %2;" : "=f"(f.x), "=f"(f.y) : "l"(x));
    return f;
}

__global__ __launch_bounds__(BLOCK, 3)
void temporal_agg_kernel(const float* __restrict__ val,
                         const float* __restrict__ b_lin,
                         float* __restrict__ out,
                         int rows_total) {
    __shared__ float sval[WARPS][26 * STRIDE];  // padded: rows 0 and 25 are zero halo

    const int warp = threadIdx.x >> 5;
    const int lane = threadIdx.x & 31;
    const int tg   = lane >> 3;        // 0..3 -> t-tile of 6
    const int o2g  = lane & 7;         // 0..7 -> 8 channels (4 f32 pairs)
    const int tbase  = tg * 6;
    const int o2base = o2g * 8;

    const int row = blockIdx.x * WARPS + warp;
    if (row >= rows_total) return;     // warp-uniform exit

    float* sv = sval[warp];

    // zero halo rows (padded t = 0 and 25)
    for (int i = lane; i < D; i += 32) {
        sv[i] = 0.f;
        sv[25 * STRIDE + i] = 0.f;
    }
    // stage this warp's row: 1536 floats as float4, coalesced LDG.128
    {
        const float4* src = (const float4*)(val + (size_t)row * (T * D));
#pragma unroll
        for (int idx = lane; idx < (T * D) / 4; idx += 32) {
            float4 x = src[idx];
            int e = idx * 4;
            int t = e >> 6, i = e & 63;
            *(float4*)(sv + (t + 1) * STRIDE + i) = x;   // 16B aligned: STRIDE%4==0
        }
    }
    __syncwarp();

    // acc[t6][p]: f32x2 over channels (o2base+2p, o2base+2p+1), t = tbase+t6
    uint64_t acc[6][4];
#pragma unroll
    for (int t6 = 0; t6 < 6; ++t6)
#pragma unroll
        for (int p = 0; p < 4; ++p) acc[t6][p] = 0ull;

    const uint64_t* M2 = (const uint64_t*)g_M;       // pairs of adjacent o2
    const float*  vb = sv + tbase * STRIDE;          // padded row tbase == logical t-1 of tile start

#pragma unroll 2
    for (int i = 0; i < D; ++i) {
        // broadcast value loads (4 distinct addrs/warp, bank-disjoint via STRIDE) + pack
        uint64_t vv[8];
#pragma unroll
        for (int j = 0; j < 8; ++j) vv[j] = pack2(vb[j * STRIDE + i]);

        // 12 L1-resident LDG.64 weight pairs
        uint64_t m[KW][4];
#pragma unroll
        for (int k = 0; k < KW; ++k)
#pragma unroll
            for (int p = 0; p < 4; ++p)
                m[k][p] = __ldg(M2 + (size_t)(k * D + i) * 32 + o2g * 4 + p);

        // 72 FFMA2 = 144 FMA
#pragma unroll
        for (int k = 0; k < KW; ++k)
#pragma unroll
            for (int t6 = 0; t6 < 6; ++t6)
#pragma unroll
                for (int p = 0; p < 4; ++p)
                    fma2(acc[t6][p], m[k][p], vv[t6 + k]);
    }

    // cross-tile band neighbors via shuffle: g[tbase-1] from tg-1 (acc[5]), g[tbase+6] from tg+1 (acc[0])
    const unsigned FULL = 0xffffffffu;
    uint64_t up[4], dn[4];
#pragma unroll
    for (int p = 0; p < 4; ++p) {
        up[p] = __shfl_sync(FULL, acc[5][p], (lane - 8) & 31);
        dn[p] = __shfl_sync(FULL, acc[0][p], (lane + 8) & 31);
    }

    // per-channel combined biases
    float b3[8], b2[8];
#pragma unroll
    for (int c = 0; c < 8; ++c) {
        float cc = g_c[o2base + c];
        float bl = __ldg(b_lin + o2base + c);
        b3[c] = fmaf(3.f, cc, bl);
        b2[c] = fmaf(2.f, cc, bl);
    }

    float* orow = out + (size_t)row * (T * D) + o2base;
#pragma unroll
    for (int t6 = 0; t6 < 6; ++t6) {
        const int t = tbase + t6;
        float r[8];
#pragma unroll
        for (int p = 0; p < 4; ++p) {
            uint64_t pr = (t6 > 0) ? acc[t6 - 1][p] : ((tg > 0) ? up[p] : 0ull);
            uint64_t nx = (t6 < 5) ? acc[t6 + 1][p] : ((tg < 3) ? dn[p] : 0ull);
            float2 a = as_f2(acc[t6][p]);
            float2 q = as_f2(pr);
            float2 w = as_f2(nx);
            float z0 = a.x + q.x + w.x;
            float z1 = a.y + q.y + w.y;
            const bool edge = (t == 0) || (t == T - 1);
            r[2 * p]     = fmaxf(z0 + (edge ? b2[2 * p]     : b3[2 * p]),     0.f);
            r[2 * p + 1] = fmaxf(z1 + (edge ? b2[2 * p + 1] : b3[2 * p + 1]), 0.f);
        }
        float4* o4 = (float4*)(orow + t * D);
        o4[0] = make_float4(r[0], r[1], r[2], r[3]);
        o4[1] = make_float4(r[4], r[5], r[6], r[7]);
    }
}

extern "C" void kernel_launch(void* const* d_in, const int* in_sizes, int n_in,
                              void* d_out, int out_size) {
    const float* value  = (const float*)d_in[0];
    const float* W_conv = (const float*)d_in[1];
    const float* b_conv = (const float*)d_in[2];
    const float* W_lin  = (const float*)d_in[3];
    const float* b_lin  = (const float*)d_in[4];
    float* out = (float*)d_out;

    const int rows_total = in_sizes[0] / (T * D);   // B*N = 16384

    prep_kernel<<<(KW * D * D + 255) / 256, 256>>>(W_conv, b_conv, W_lin);

    const int grid = (rows_total + WARPS - 1) / WARPS;
    temporal_agg_kernel<<<grid, BLOCK>>>(value, b_lin, out, rows_total);
}